// round 12
// baseline (speedup 1.0000x reference)
#include <cuda_runtime.h>
#include <cuda_bf16.h>
#include <cuda_fp16.h>
#include <cstdint>

#define B_ 8
#define C_ 1024
#define T_ 2048
#define S_ 2048
#define E_ 1024

typedef __nv_bfloat16 bf16;

// ---------------- scratch (__device__ globals: allocation-free rule) -------
__device__ bf16 g_convT_h[(size_t)B_*T_*C_];
__device__ bf16 g_convT_l[(size_t)B_*T_*C_];
__device__ bf16 g_wh2e_h[(size_t)E_*C_];
__device__ bf16 g_wh2e_l[(size_t)E_*C_];
__device__ bf16 g_encK_h[(size_t)B_*S_*E_];
__device__ bf16 g_encK_l[(size_t)B_*S_*E_];
__device__ bf16 g_comb_h[(size_t)B_*T_*E_];
__device__ bf16 g_comb_l[(size_t)B_*T_*E_];
__device__ __half g_attn_h[(size_t)B_*T_*S_];   // fp16 single (V-path)
__device__ __half g_encVT_h[(size_t)B_*E_*S_];
__device__ __half g_attd_h[(size_t)B_*T_*E_];
__device__ __half g_we2h_h[(size_t)C_*E_];

// ---------------- helpers ----------------------------------------------------
__device__ __forceinline__ uint32_t smem_u32(const void* p) {
    uint32_t a;
    asm("{ .reg .u64 t; cvta.to.shared.u64 t, %1; cvt.u32.u64 %0, t; }"
        : "=r"(a) : "l"(p));
    return a;
}
__device__ __forceinline__ void cp16(uint32_t dst, const void* src) {
    asm volatile("cp.async.cg.shared.global [%0], [%1], 16;"
                 :: "r"(dst), "l"(src) : "memory");
}
__device__ __forceinline__ void mbar_init(uint32_t a, uint32_t cnt) {
    asm volatile("mbarrier.init.shared.b64 [%0], %1;" :: "r"(a), "r"(cnt) : "memory");
}
__device__ __forceinline__ void mbar_arrive(uint32_t a) {
    asm volatile("mbarrier.arrive.shared::cta.b64 _, [%0];" :: "r"(a) : "memory");
}
__device__ __forceinline__ void cpasync_arrive(uint32_t a) {
    asm volatile("cp.async.mbarrier.arrive.noinc.shared::cta.b64 [%0];"
                 :: "r"(a) : "memory");
}
__device__ __forceinline__ void mbar_wait(uint32_t a, uint32_t parity) {
    uint32_t done;
    do {
        asm volatile("{\n\t.reg .pred p;\n\t"
            "mbarrier.try_wait.parity.acquire.cta.shared::cta.b64 p, [%1], %2, 0x989680;\n\t"
            "selp.b32 %0, 1, 0, p;\n\t}"
            : "=r"(done) : "r"(a), "r"(parity) : "memory");
    } while (!done);
}
__device__ __forceinline__ void ldsm4(uint32_t* r, uint32_t a) {
    asm volatile("ldmatrix.sync.aligned.m8n8.x4.shared.b16 {%0,%1,%2,%3}, [%4];"
        : "=r"(r[0]), "=r"(r[1]), "=r"(r[2]), "=r"(r[3]) : "r"(a));
}
__device__ __forceinline__ void mma_bf(float* d, const uint32_t* a, const uint32_t* b) {
    asm volatile("mma.sync.aligned.m16n8k16.row.col.f32.bf16.bf16.f32 "
        "{%0,%1,%2,%3}, {%4,%5,%6,%7}, {%8,%9}, {%0,%1,%2,%3};"
        : "+f"(d[0]), "+f"(d[1]), "+f"(d[2]), "+f"(d[3])
        : "r"(a[0]), "r"(a[1]), "r"(a[2]), "r"(a[3]), "r"(b[0]), "r"(b[1]));
}
__device__ __forceinline__ void mma_fp(float* d, const uint32_t* a, const uint32_t* b) {
    asm volatile("mma.sync.aligned.m16n8k16.row.col.f32.f16.f16.f32 "
        "{%0,%1,%2,%3}, {%4,%5,%6,%7}, {%8,%9}, {%0,%1,%2,%3};"
        : "+f"(d[0]), "+f"(d[1]), "+f"(d[2]), "+f"(d[3])
        : "r"(a[0]), "r"(a[1]), "r"(a[2]), "r"(a[3]), "r"(b[0]), "r"(b[1]));
}
__device__ __forceinline__ uint32_t sw(uint32_t bo) {  // SW128 swizzle
    return bo ^ ((bo >> 3) & 0x70);
}

// CTA tile 128(m) x 64(n), K-chunk 64.
// SPLIT: 4 warps as 2(m)x2(n), warp tile 64x32, 128 threads, phased hi/lo frags.
// SINGLE: 8 warps as 4(m)x2(n), warp tile 32x32, 256 threads.
#define TILE_A 16384             // 128 rows x 64 elems x 2B
#define TILE_B 8192              // 64 rows x 64 elems x 2B
#define MBAR_ZONE 1024
// split: 2 stages x 48KB = 96KB; single: 4 stages x 24KB = 96KB
#define SMEM_GEMM (1024 + MBAR_ZONE + 98304)

// async-load ROWS x 64 x16b tile (k-contiguous source) into swizzled smem
template <int ROWS, int NTH>
__device__ __forceinline__ void load_tile_async(const bf16* __restrict__ src,
                                                int row0, int ld, int k0,
                                                uint32_t sdst, int tid) {
#pragma unroll
    for (int r = 0; r < ROWS * 8 / NTH; r++) {
        int c = tid + r * NTH;            // 16B chunks
        int row = c >> 3, seg = c & 7;
        uint32_t bo = (uint32_t)(row * 128 + seg * 16);
        cp16(sdst + sw(bo), src + (size_t)(row0 + row) * ld + k0 + seg * 8);
    }
}

// ---------------- GEMM args --------------------------------------------------
struct GemmArgs {
    const bf16 *Ah, *Al, *Bh, *Bl;   // 16-bit payload; type per SPLIT
    long sA, sB;
    int lda, ldb, nChunks;
    float* outF;
    bf16 *outH, *outL;
    const float *bias, *xres, *scale, *conved;
};

// SPLIT=1: bf16 3-term split (2-stage pipe, 128 thr). SPLIT=0: fp16 single (4-stage, 256 thr).
// MODE: 0 comb (bias+x,*scale -> bf16 hi/lo), 1 energy (fp32),
//       2 attd (fp16 single),  3 outproj (transposed +bias+residual fp32)
template <int SPLIT, int MODE>
__global__ __launch_bounds__((SPLIT ? 128 : 256), 2) void mma_gemm(GemmArgs g) {
    extern __shared__ char sraw[];
    uint32_t sb0 = smem_u32(sraw);
    uint32_t sbase = (sb0 + 1023) & ~1023u;
    char* sgen = sraw + (sbase - sb0);

    constexpr int NTH = SPLIT ? 128 : 256;
    constexpr int STAGES = SPLIT ? 2 : 4;
    constexpr int MT = SPLIT ? 4 : 2;     // 16-row m-tiles per warp
    constexpr uint32_t BUFSZ = SPLIT ? (2 * TILE_A + 2 * TILE_B) : (TILE_A + TILE_B);

    const int tid = threadIdx.x;
    const int m0 = blockIdx.x * 128, n0 = blockIdx.y * 64, b = blockIdx.z;

    const bf16* Ah = g.Ah + (size_t)b * g.sA;
    const bf16* Al = SPLIT ? g.Al + (size_t)b * g.sA : nullptr;
    const bf16* Bh = g.Bh + (size_t)b * g.sB;
    const bf16* Bl = SPLIT ? g.Bl + (size_t)b * g.sB : nullptr;

    const int wid = tid >> 5, lane = tid & 31;
    // SPLIT: 2x2 warps, warp tile 64x32. SINGLE: 4x2 warps, warp tile 32x32.
    const int wm = SPLIT ? (wid & 1) * 64 : (wid & 3) * 32;
    const int wn = SPLIT ? (wid >> 1) * 32 : (wid >> 2) * 32;

    // init pipeline mbarriers (full/empty per stage)
    if (tid == 0) {
#pragma unroll
        for (int s = 0; s < STAGES; s++) {
            mbar_init(sbase + s * 16,     NTH);  // full
            mbar_init(sbase + s * 16 + 8, NTH);  // empty
        }
    }
    __syncthreads();

    float acc[MT][4][4];
#pragma unroll
    for (int i = 0; i < MT; i++)
#pragma unroll
        for (int j = 0; j < 4; j++)
#pragma unroll
            for (int k = 0; k < 4; k++) acc[i][j][k] = 0.f;

    // issue loads for chunk i + signal full[i%STAGES] on completion
    auto load = [&](int i) {
        int k0 = i * 64;
        int bu = i % STAGES;
        uint32_t off = sbase + MBAR_ZONE + (uint32_t)bu * BUFSZ;
        if (SPLIT) {
            load_tile_async<128, NTH>(Ah, m0, g.lda, k0, off,                       tid);
            load_tile_async<128, NTH>(Al, m0, g.lda, k0, off + TILE_A,              tid);
            load_tile_async<64,  NTH>(Bh, n0, g.ldb, k0, off + 2 * TILE_A,          tid);
            load_tile_async<64,  NTH>(Bl, n0, g.ldb, k0, off + 2 * TILE_A + TILE_B, tid);
        } else {
            load_tile_async<128, NTH>(Ah, m0, g.lda, k0, off,          tid);
            load_tile_async<64,  NTH>(Bh, n0, g.ldb, k0, off + TILE_A, tid);
        }
        cpasync_arrive(sbase + (uint32_t)bu * 16);
    };

    // base swizzled offsets (ks=0); per-ks via XOR (ks*32) - disjoint bit field
    uint32_t aoff0[MT], boff0[2];
#pragma unroll
    for (int mt = 0; mt < MT; mt++)
        aoff0[mt] = sw((uint32_t)((wm + mt * 16 + (lane & 15)) * 128 +
                                   (lane >> 4) * 16));
#pragma unroll
    for (int np = 0; np < 2; np++)
        boff0[np] = sw((uint32_t)((wn + np * 16 + (lane & 7) + (lane >> 4) * 8) * 128 +
                                   ((lane >> 3) & 1) * 16));

    const int nch = g.nChunks;
#pragma unroll
    for (int p = 0; p < STAGES - 1; p++)
        if (p < nch) load(p);

    for (int i = 0; i < nch; i++) {
        const int bu = i % STAGES;
        const uint32_t ph = (uint32_t)((i / STAGES) & 1);
        mbar_wait(sbase + (uint32_t)bu * 16, ph);   // data of chunk i ready

        uint32_t base = sbase + MBAR_ZONE + (uint32_t)bu * BUFSZ;
        uint32_t aHp = base, aLp = base + TILE_A;
        uint32_t bHp = base + (SPLIT ? 2 * TILE_A : TILE_A);
        uint32_t bLp = base + 2 * TILE_A + TILE_B;

#pragma unroll
        for (int ks = 0; ks < 4; ks++) {
            const uint32_t kx = (uint32_t)(ks * 32);

            if (SPLIT) {
                // ---- phase 1: Ah x Bh ----
                uint32_t Ahr[MT][4], Bhr[4][2];
#pragma unroll
                for (int mt = 0; mt < MT; mt++)
                    ldsm4(Ahr[mt], aHp + (aoff0[mt] ^ kx));
#pragma unroll
                for (int np = 0; np < 2; np++) {
                    uint32_t q[4];
                    ldsm4(q, bHp + (boff0[np] ^ kx));
                    Bhr[np * 2][0] = q[0]; Bhr[np * 2][1] = q[1];
                    Bhr[np * 2 + 1][0] = q[2]; Bhr[np * 2 + 1][1] = q[3];
                }
#pragma unroll
                for (int mt = 0; mt < MT; mt++)
#pragma unroll
                    for (int nt = 0; nt < 4; nt++)
                        mma_bf(acc[mt][nt], Ahr[mt], Bhr[nt]);

                // producer: stage chunk i + STAGES-1 (hidden behind MMAs)
                if (ks == 0) {
                    int j = i + STAGES - 1;
                    if (j < nch) {
                        int pj = j / STAGES;
                        if (pj > 0)
                            mbar_wait(sbase + (uint32_t)(j % STAGES) * 16 + 8,
                                      (uint32_t)((pj - 1) & 1));
                        load(j);
                    }
                }

                // ---- phase 2: Al x Bh ----
                uint32_t Alr[MT][4];
#pragma unroll
                for (int mt = 0; mt < MT; mt++)
                    ldsm4(Alr[mt], aLp + (aoff0[mt] ^ kx));
#pragma unroll
                for (int mt = 0; mt < MT; mt++)
#pragma unroll
                    for (int nt = 0; nt < 4; nt++)
                        mma_bf(acc[mt][nt], Alr[mt], Bhr[nt]);

                // ---- phase 3: Ah x Bl ----
                uint32_t Blr[4][2];
#pragma unroll
                for (int np = 0; np < 2; np++) {
                    uint32_t q[4];
                    ldsm4(q, bLp + (boff0[np] ^ kx));
                    Blr[np * 2][0] = q[0]; Blr[np * 2][1] = q[1];
                    Blr[np * 2 + 1][0] = q[2]; Blr[np * 2 + 1][1] = q[3];
                }
                if (ks == 3)   // last read of buffer bu by this thread
                    mbar_arrive(sbase + (uint32_t)bu * 16 + 8);
#pragma unroll
                for (int mt = 0; mt < MT; mt++)
#pragma unroll
                    for (int nt = 0; nt < 4; nt++)
                        mma_bf(acc[mt][nt], Ahr[mt], Blr[nt]);
            } else {
                uint32_t Ahr[MT][4], Bhr[4][2];
#pragma unroll
                for (int mt = 0; mt < MT; mt++)
                    ldsm4(Ahr[mt], aHp + (aoff0[mt] ^ kx));
#pragma unroll
                for (int np = 0; np < 2; np++) {
                    uint32_t q[4];
                    ldsm4(q, bHp + (boff0[np] ^ kx));
                    Bhr[np * 2][0] = q[0]; Bhr[np * 2][1] = q[1];
                    Bhr[np * 2 + 1][0] = q[2]; Bhr[np * 2 + 1][1] = q[3];
                }
                if (ks == 3)
                    mbar_arrive(sbase + (uint32_t)bu * 16 + 8);
#pragma unroll
                for (int mt = 0; mt < MT; mt++)
#pragma unroll
                    for (int nt = 0; nt < 4; nt++)
                        mma_fp(acc[mt][nt], Ahr[mt], Bhr[nt]);

                if (ks == 0) {
                    int j = i + STAGES - 1;
                    if (j < nch) {
                        int pj = j / STAGES;
                        if (pj > 0)
                            mbar_wait(sbase + (uint32_t)(j % STAGES) * 16 + 8,
                                      (uint32_t)((pj - 1) & 1));
                        load(j);
                    }
                }
            }
        }
    }
    __syncthreads();   // all warps done with tile buffers before stg reuse

    // ---- epilogue: stage through smem for coalesced writes (128 x 68 f32) ----
    float* stg = (float*)(sgen + MBAR_ZONE);
#pragma unroll
    for (int mt = 0; mt < MT; mt++)
#pragma unroll
        for (int nt = 0; nt < 4; nt++) {
            int r = wm + mt * 16 + (lane >> 2);
            int c = wn + nt * 8 + (lane & 3) * 2;
            stg[r * 68 + c]           = acc[mt][nt][0];
            stg[r * 68 + c + 1]       = acc[mt][nt][1];
            stg[(r + 8) * 68 + c]     = acc[mt][nt][2];
            stg[(r + 8) * 68 + c + 1] = acc[mt][nt][3];
        }
    __syncthreads();

    if (MODE == 0) {
        const float sc = g.scale[0];
        for (int e = tid; e < 128 * 64; e += NTH) {
            int m = e >> 6, n = e & 63;
            size_t o = ((size_t)b * T_ + m0 + m) * E_ + n0 + n;
            float v = (stg[m * 68 + n] + g.bias[n0 + n] + g.xres[o]) * sc;
            bf16 h = __float2bfloat16(v);
            g.outH[o] = h;
            g.outL[o] = __float2bfloat16(v - __bfloat162float(h));
        }
    } else if (MODE == 1) {
        for (int e = tid; e < 128 * 64; e += NTH) {
            int m = e >> 6, n = e & 63;
            g.outF[((size_t)b * T_ + m0 + m) * S_ + n0 + n] = stg[m * 68 + n];
        }
    } else if (MODE == 2) {
        __half* oh = (__half*)g.outH;
        for (int e = tid; e < 128 * 64; e += NTH) {
            int m = e >> 6, n = e & 63;
            size_t o = ((size_t)b * T_ + m0 + m) * E_ + n0 + n;
            oh[o] = __float2half(stg[m * 68 + n]);
        }
    } else {
        for (int e = tid; e < 128 * 64; e += NTH) {
            int n = e >> 7, m = e & 127;   // m fastest -> coalesced transposed store
            size_t o = ((size_t)b * C_ + n0 + n) * T_ + m0 + m;
            g.outF[o] = stg[m * 68 + n] + g.bias[n0 + n] + g.conved[o];
        }
    }
}

// ---------------- aux kernels -----------------------------------------------
// bf16 hi/lo split for two arrays in one launch
__global__ __launch_bounds__(256) void convert_split2(
    const float4* __restrict__ in0, bf16* __restrict__ oh0, bf16* __restrict__ ol0, size_t n0,
    const float4* __restrict__ in1, bf16* __restrict__ oh1, bf16* __restrict__ ol1, size_t n1)
{
    size_t i = (size_t)blockIdx.x * 256 + threadIdx.x;
    const float4* in; bf16 *oh, *ol;
    if (i < n0)           { in = in0; oh = oh0; ol = ol0; }
    else if (i < n0 + n1) { i -= n0; in = in1; oh = oh1; ol = ol1; }
    else return;
    float4 f = in[i];
    bf16 h0 = __float2bfloat16(f.x), h1 = __float2bfloat16(f.y);
    bf16 h2 = __float2bfloat16(f.z), h3 = __float2bfloat16(f.w);
    ((__nv_bfloat162*)oh)[2 * i]     = {h0, h1};
    ((__nv_bfloat162*)oh)[2 * i + 1] = {h2, h3};
    ((__nv_bfloat162*)ol)[2 * i] =
        {__float2bfloat16(f.x - __bfloat162float(h0)),
         __float2bfloat16(f.y - __bfloat162float(h1))};
    ((__nv_bfloat162*)ol)[2 * i + 1] =
        {__float2bfloat16(f.z - __bfloat162float(h2)),
         __float2bfloat16(f.w - __bfloat162float(h3))};
}

// fp16 single convert
__global__ __launch_bounds__(256) void convert_half(const float4* __restrict__ in,
                                                    __half* __restrict__ oh, size_t n4) {
    size_t i = (size_t)blockIdx.x * 256 + threadIdx.x;
    if (i >= n4) return;
    float4 f = in[i];
    ((__half2*)oh)[2 * i]     = {__float2half(f.x), __float2half(f.y)};
    ((__half2*)oh)[2 * i + 1] = {__float2half(f.z), __float2half(f.w)};
}

// in: [B][R][C] fp32 -> out: [B][C][R] bf16 hi/lo
__global__ __launch_bounds__(256) void transpose_split(const float* __restrict__ in,
                                                       bf16* __restrict__ oh,
                                                       bf16* __restrict__ ol,
                                                       int R, int C) {
    __shared__ float tile[32][33];
    const int bz = blockIdx.z;
    const float* src = in + (size_t)bz * R * C;
    const size_t ob = (size_t)bz * R * C;
    const int c0 = blockIdx.x * 32, r0 = blockIdx.y * 32;
    const int tx = threadIdx.x & 31, ty = threadIdx.x >> 5;
#pragma unroll
    for (int i = 0; i < 4; i++)
        tile[ty + i * 8][tx] = src[(size_t)(r0 + ty + i * 8) * C + c0 + tx];
    __syncthreads();
#pragma unroll
    for (int i = 0; i < 4; i++) {
        float v = tile[tx][ty + i * 8];
        size_t o = ob + (size_t)(c0 + ty + i * 8) * R + r0 + tx;
        bf16 h = __float2bfloat16(v);
        oh[o] = h;
        ol[o] = __float2bfloat16(v - __bfloat162float(h));
    }
}

// in: [B][R][C] fp32 -> out: [B][C][R] fp16
__global__ __launch_bounds__(256) void transpose_half(const float* __restrict__ in,
                                                      __half* __restrict__ oh,
                                                      int R, int C) {
    __shared__ float tile[32][33];
    const int bz = blockIdx.z;
    const float* src = in + (size_t)bz * R * C;
    const size_t ob = (size_t)bz * R * C;
    const int c0 = blockIdx.x * 32, r0 = blockIdx.y * 32;
    const int tx = threadIdx.x & 31, ty = threadIdx.x >> 5;
#pragma unroll
    for (int i = 0; i < 4; i++)
        tile[ty + i * 8][tx] = src[(size_t)(r0 + ty + i * 8) * C + c0 + tx];
    __syncthreads();
#pragma unroll
    for (int i = 0; i < 4; i++) {
        float v = tile[tx][ty + i * 8];
        size_t o = ob + (size_t)(c0 + ty + i * 8) * R + r0 + tx;
        oh[o] = __float2half(v);
    }
}

__global__ __launch_bounds__(256) void softmax_split(float* __restrict__ att,
                                                     __half* __restrict__ oh) {
    const size_t rb = (size_t)blockIdx.x * S_;
    float* p = att + rb;
    const int tid = threadIdx.x;
    __shared__ float red[8];

    float v[8];
    float mx = -1e30f;
#pragma unroll
    for (int i = 0; i < 8; i++) { v[i] = p[tid + i * 256]; mx = fmaxf(mx, v[i]); }
#pragma unroll
    for (int o = 16; o; o >>= 1) mx = fmaxf(mx, __shfl_xor_sync(0xffffffffu, mx, o));
    if ((tid & 31) == 0) red[tid >> 5] = mx;
    __syncthreads();
    float bm = red[0];
#pragma unroll
    for (int wi = 1; wi < 8; wi++) bm = fmaxf(bm, red[wi]);
    __syncthreads();

    float sum = 0.f;
#pragma unroll
    for (int i = 0; i < 8; i++) { v[i] = __expf(v[i] - bm); sum += v[i]; }
#pragma unroll
    for (int o = 16; o; o >>= 1) sum += __shfl_xor_sync(0xffffffffu, sum, o);
    if ((tid & 31) == 0) red[tid >> 5] = sum;
    __syncthreads();
    float bs = 0.f;
#pragma unroll
    for (int wi = 0; wi < 8; wi++) bs += red[wi];
    const float inv = 1.f / bs;
#pragma unroll
    for (int i = 0; i < 8; i++) {
        float pv = v[i] * inv;
        size_t o = rb + tid + i * 256;
        att[o] = pv;
        oh[o] = __float2half(pv);
    }
}

// ---------------- host -------------------------------------------------------
extern "C" void kernel_launch(void* const* d_in, const int* in_sizes, int n_in,
                              void* d_out, int out_size) {
    (void)in_sizes; (void)n_in; (void)out_size;
    const float* conved   = (const float*)d_in[0];
    const float* enc_conv = (const float*)d_in[1];
    const float* enc_comb = (const float*)d_in[2];
    const float* x        = (const float*)d_in[3];
    const float* scale    = (const float*)d_in[4];
    const float* W_h2e    = (const float*)d_in[5];
    const float* b_h2e    = (const float*)d_in[6];
    const float* W_e2h    = (const float*)d_in[7];
    const float* b_e2h    = (const float*)d_in[8];

    float* attn = (float*)d_out;
    float* out2 = (float*)d_out + (size_t)B_ * T_ * S_;

    bf16 *convT_h, *convT_l, *wh2e_h, *wh2e_l, *encK_h, *encK_l, *comb_h, *comb_l;
    __half *attn_h, *encVT_h, *attd_h, *we2h_h;
    cudaGetSymbolAddress((void**)&convT_h, g_convT_h);
    cudaGetSymbolAddress((void**)&convT_l, g_convT_l);
    cudaGetSymbolAddress((void**)&wh2e_h,  g_wh2e_h);
    cudaGetSymbolAddress((void**)&wh2e_l,  g_wh2e_l);
    cudaGetSymbolAddress((void**)&encK_h,  g_encK_h);
    cudaGetSymbolAddress((void**)&encK_l,  g_encK_l);
    cudaGetSymbolAddress((void**)&comb_h,  g_comb_h);
    cudaGetSymbolAddress((void**)&comb_l,  g_comb_l);
    cudaGetSymbolAddress((void**)&attn_h,  g_attn_h);
    cudaGetSymbolAddress((void**)&encVT_h, g_encVT_h);
    cudaGetSymbolAddress((void**)&attd_h,  g_attd_h);
    cudaGetSymbolAddress((void**)&we2h_h,  g_we2h_h);

    cudaFuncSetAttribute(mma_gemm<1,0>, cudaFuncAttributeMaxDynamicSharedMemorySize, SMEM_GEMM);
    cudaFuncSetAttribute(mma_gemm<1,1>, cudaFuncAttributeMaxDynamicSharedMemorySize, SMEM_GEMM);
    cudaFuncSetAttribute(mma_gemm<0,2>, cudaFuncAttributeMaxDynamicSharedMemorySize, SMEM_GEMM);
    cudaFuncSetAttribute(mma_gemm<0,3>, cudaFuncAttributeMaxDynamicSharedMemorySize, SMEM_GEMM);

    // --- preprocessing needed before G1/G2 ---
    transpose_split<<<dim3(T_/32, C_/32, B_), 256>>>(conved, convT_h, convT_l, C_, T_);
    {
        size_t n4w = (size_t)E_ * C_ / 4;
        size_t n4e = (size_t)B_ * S_ * E_ / 4;
        convert_split2<<<(unsigned)((n4w + n4e + 255) / 256), 256>>>(
            (const float4*)W_h2e, wh2e_h, wh2e_l, n4w,
            (const float4*)enc_conv, encK_h, encK_l, n4e);
        convert_half<<<(unsigned)((n4w + 255) / 256), 256>>>(
            (const float4*)W_e2h, we2h_h, n4w);
    }

    GemmArgs a{};

    // Stage 1 (bf16 split): comb = (convT @ W_h2e^T + b + x) * scale
    a = GemmArgs{convT_h, convT_l, wh2e_h, wh2e_l,
                 (long)T_ * C_, 0L, C_, C_, C_ / 64,
                 nullptr, comb_h, comb_l, b_h2e, x, scale, nullptr};
    mma_gemm<1,0><<<dim3(T_/128, E_/64, B_), 128, SMEM_GEMM>>>(a);

    // Stage 2 (bf16 split): energy = comb @ enc_conved^T -> fp32 in d_out
    a = GemmArgs{comb_h, comb_l, encK_h, encK_l,
                 (long)T_ * E_, (long)S_ * E_, E_, E_, E_ / 64,
                 attn, nullptr, nullptr, nullptr, nullptr, nullptr, nullptr};
    mma_gemm<1,1><<<dim3(T_/128, S_/64, B_), 128, SMEM_GEMM>>>(a);

    // Stage 3: softmax in place + fp16
    softmax_split<<<B_ * T_, 256>>>(attn, attn_h);

    // encVT transpose (fp16) only needed by stage 4
    transpose_half<<<dim3(E_/32, S_/32, B_), 256>>>(enc_comb, encVT_h, S_, E_);

    // Stage 4 (fp16 single): attended = attn @ enc_combined -> fp16
    a = GemmArgs{(const bf16*)attn_h, nullptr, (const bf16*)encVT_h, nullptr,
                 (long)T_ * S_, (long)E_ * S_, S_, S_, S_ / 64,
                 nullptr, (bf16*)attd_h, nullptr, nullptr, nullptr, nullptr, nullptr};
    mma_gemm<0,2><<<dim3(T_/128, E_/64, B_), 256, SMEM_GEMM>>>(a);

    // Stage 5 (fp16 single): out2[b,c,t] = attd @ W_e2h^T + b_e2h + conved
    a = GemmArgs{(const bf16*)attd_h, nullptr, (const bf16*)we2h_h, nullptr,
                 (long)T_ * E_, 0L, E_, E_, E_ / 64,
                 out2, nullptr, nullptr, b_e2h, nullptr, nullptr, conved};
    mma_gemm<0,3><<<dim3(T_/128, C_/64, B_), 256, SMEM_GEMM>>>(a);
}

// round 13
// speedup vs baseline: 1.1625x; 1.1625x over previous
#include <cuda_runtime.h>
#include <cuda_bf16.h>
#include <cuda_fp16.h>
#include <cstdint>

#define B_ 8
#define C_ 1024
#define T_ 2048
#define S_ 2048
#define E_ 1024

typedef __nv_bfloat16 bf16;

// ---------------- scratch (__device__ globals: allocation-free rule) -------
__device__ bf16 g_convT_h[(size_t)B_*T_*C_];
__device__ bf16 g_convT_l[(size_t)B_*T_*C_];
__device__ bf16 g_wh2e_h[(size_t)E_*C_];
__device__ bf16 g_wh2e_l[(size_t)E_*C_];
__device__ bf16 g_encK_h[(size_t)B_*S_*E_];
__device__ bf16 g_encK_l[(size_t)B_*S_*E_];
__device__ bf16 g_comb_h[(size_t)B_*T_*E_];
__device__ bf16 g_comb_l[(size_t)B_*T_*E_];
__device__ __half g_attn_h[(size_t)B_*T_*S_];   // fp16 single (V-path)
__device__ __half g_encVT_h[(size_t)B_*E_*S_];
__device__ __half g_attd_h[(size_t)B_*T_*E_];
__device__ __half g_we2h_h[(size_t)C_*E_];

// ---------------- helpers ----------------------------------------------------
__device__ __forceinline__ uint32_t smem_u32(const void* p) {
    uint32_t a;
    asm("{ .reg .u64 t; cvta.to.shared.u64 t, %1; cvt.u32.u64 %0, t; }"
        : "=r"(a) : "l"(p));
    return a;
}
__device__ __forceinline__ void cp16(uint32_t dst, const void* src) {
    asm volatile("cp.async.cg.shared.global [%0], [%1], 16;"
                 :: "r"(dst), "l"(src) : "memory");
}
__device__ __forceinline__ void mbar_init(uint32_t a, uint32_t cnt) {
    asm volatile("mbarrier.init.shared.b64 [%0], %1;" :: "r"(a), "r"(cnt) : "memory");
}
__device__ __forceinline__ void mbar_arrive(uint32_t a) {
    asm volatile("mbarrier.arrive.shared::cta.b64 _, [%0];" :: "r"(a) : "memory");
}
__device__ __forceinline__ void cpasync_arrive(uint32_t a) {
    asm volatile("cp.async.mbarrier.arrive.noinc.shared::cta.b64 [%0];"
                 :: "r"(a) : "memory");
}
__device__ __forceinline__ void mbar_wait(uint32_t a, uint32_t parity) {
    uint32_t done;
    do {
        asm volatile("{\n\t.reg .pred p;\n\t"
            "mbarrier.try_wait.parity.acquire.cta.shared::cta.b64 p, [%1], %2, 0x989680;\n\t"
            "selp.b32 %0, 1, 0, p;\n\t}"
            : "=r"(done) : "r"(a), "r"(parity) : "memory");
    } while (!done);
}
__device__ __forceinline__ void ldsm4(uint32_t* r, uint32_t a) {
    asm volatile("ldmatrix.sync.aligned.m8n8.x4.shared.b16 {%0,%1,%2,%3}, [%4];"
        : "=r"(r[0]), "=r"(r[1]), "=r"(r[2]), "=r"(r[3]) : "r"(a));
}
__device__ __forceinline__ void mma_bf(float* d, const uint32_t* a, const uint32_t* b) {
    asm volatile("mma.sync.aligned.m16n8k16.row.col.f32.bf16.bf16.f32 "
        "{%0,%1,%2,%3}, {%4,%5,%6,%7}, {%8,%9}, {%0,%1,%2,%3};"
        : "+f"(d[0]), "+f"(d[1]), "+f"(d[2]), "+f"(d[3])
        : "r"(a[0]), "r"(a[1]), "r"(a[2]), "r"(a[3]), "r"(b[0]), "r"(b[1]));
}
__device__ __forceinline__ void mma_fp(float* d, const uint32_t* a, const uint32_t* b) {
    asm volatile("mma.sync.aligned.m16n8k16.row.col.f32.f16.f16.f32 "
        "{%0,%1,%2,%3}, {%4,%5,%6,%7}, {%8,%9}, {%0,%1,%2,%3};"
        : "+f"(d[0]), "+f"(d[1]), "+f"(d[2]), "+f"(d[3])
        : "r"(a[0]), "r"(a[1]), "r"(a[2]), "r"(a[3]), "r"(b[0]), "r"(b[1]));
}
__device__ __forceinline__ uint32_t sw(uint32_t bo) {  // SW128 swizzle
    return bo ^ ((bo >> 3) & 0x70);
}

// SPLIT (bf16 3-term): CTA 128x64, 8 warps 4(m)x2(n), warp 32x32, 2-stage pipe.
// SINGLE (fp16):       CTA 128x128, 8 warps 4(m)x2(n), warp 32x64, 3-stage pipe.
// Both: 256 threads, 2 CTAs/SM.
#define NTHREADS 256
#define TILE_A 16384             // 128 rows x 64 elems x 2B
#define MBAR_ZONE 1024
#define SMEM_GEMM (1024 + MBAR_ZONE + 98304)

// async-load ROWS x 64 x16b tile (k-contiguous source) into swizzled smem
template <int ROWS>
__device__ __forceinline__ void load_tile_async(const bf16* __restrict__ src,
                                                int row0, int ld, int k0,
                                                uint32_t sdst, int tid) {
#pragma unroll
    for (int r = 0; r < ROWS * 8 / NTHREADS; r++) {
        int c = tid + r * NTHREADS;       // 16B chunks
        int row = c >> 3, seg = c & 7;
        uint32_t bo = (uint32_t)(row * 128 + seg * 16);
        cp16(sdst + sw(bo), src + (size_t)(row0 + row) * ld + k0 + seg * 8);
    }
}

// ---------------- GEMM args --------------------------------------------------
struct GemmArgs {
    const bf16 *Ah, *Al, *Bh, *Bl;   // 16-bit payload; type per SPLIT
    long sA, sB;
    int lda, ldb, nChunks;
    float* outF;
    bf16 *outH, *outL;
    const float *bias, *xres, *scale, *conved;
};

// MODE: 0 comb (bias+x,*scale -> bf16 hi/lo), 1 energy (fp32),
//       2 attd (fp16 single),  3 outproj (transposed +bias+residual fp32)
template <int SPLIT, int MODE>
__global__ __launch_bounds__(NTHREADS, 2) void mma_gemm(GemmArgs g) {
    extern __shared__ char sraw[];
    uint32_t sb0 = smem_u32(sraw);
    uint32_t sbase = (sb0 + 1023) & ~1023u;
    char* sgen = sraw + (sbase - sb0);

    constexpr int STAGES = SPLIT ? 2 : 3;
    constexpr int NTILE  = SPLIT ? 64 : 128;   // CTA n extent
    constexpr int NTB    = SPLIT ? 4 : 8;      // 8-col n-tiles per warp
    constexpr int LDC    = SPLIT ? 68 : 132;
    constexpr uint32_t TILE_B = (uint32_t)NTILE * 128;  // bytes
    constexpr uint32_t BUFSZ = SPLIT ? (2 * TILE_A + 2 * TILE_B)   // 48KB
                                     : (TILE_A + TILE_B);          // 32KB

    const int tid = threadIdx.x;
    const int m0 = blockIdx.x * 128, n0 = blockIdx.y * NTILE, b = blockIdx.z;

    const bf16* Ah = g.Ah + (size_t)b * g.sA;
    const bf16* Al = SPLIT ? g.Al + (size_t)b * g.sA : nullptr;
    const bf16* Bh = g.Bh + (size_t)b * g.sB;
    const bf16* Bl = SPLIT ? g.Bl + (size_t)b * g.sB : nullptr;

    const int wid = tid >> 5, lane = tid & 31;
    const int wm = (wid & 3) * 32;                          // 4 m-warps
    const int wn = (wid >> 2) * (SPLIT ? 32 : 64);          // 2 n-warps

    // init pipeline mbarriers: full (cp.async-tracked, count=256),
    // empty (reader release, 1 arrive per warp -> count=8)
    if (tid == 0) {
#pragma unroll
        for (int s = 0; s < STAGES; s++) {
            mbar_init(sbase + s * 16,     NTHREADS);
            mbar_init(sbase + s * 16 + 8, 8);
        }
    }
    __syncthreads();

    float acc[2][NTB][4];
#pragma unroll
    for (int i = 0; i < 2; i++)
#pragma unroll
        for (int j = 0; j < NTB; j++)
#pragma unroll
            for (int k = 0; k < 4; k++) acc[i][j][k] = 0.f;

    // issue loads for chunk i + signal full[i%STAGES] on completion
    auto load = [&](int i) {
        int k0 = i * 64;
        int bu = i % STAGES;
        uint32_t off = sbase + MBAR_ZONE + (uint32_t)bu * BUFSZ;
        if (SPLIT) {
            load_tile_async<128>(Ah, m0, g.lda, k0, off,                        tid);
            load_tile_async<128>(Al, m0, g.lda, k0, off + TILE_A,               tid);
            load_tile_async<64> (Bh, n0, g.ldb, k0, off + 2 * TILE_A,           tid);
            load_tile_async<64> (Bl, n0, g.ldb, k0, off + 2 * TILE_A + TILE_B,  tid);
        } else {
            load_tile_async<128>(Ah, m0, g.lda, k0, off,          tid);
            load_tile_async<128>(Bh, n0, g.ldb, k0, off + TILE_A, tid);
        }
        cpasync_arrive(sbase + (uint32_t)bu * 16);
    };

    // base swizzled offsets (ks=0); per-ks via XOR (ks*32) - disjoint bit field
    uint32_t aoff0[2], boff0[NTB / 2];
#pragma unroll
    for (int mt = 0; mt < 2; mt++)
        aoff0[mt] = sw((uint32_t)((wm + mt * 16 + (lane & 15)) * 128 +
                                   (lane >> 4) * 16));
#pragma unroll
    for (int np = 0; np < NTB / 2; np++)
        boff0[np] = sw((uint32_t)((wn + np * 16 + (lane & 7) + (lane >> 4) * 8) * 128 +
                                   ((lane >> 3) & 1) * 16));

    const int nch = g.nChunks;
#pragma unroll
    for (int p = 0; p < STAGES - 1; p++)
        if (p < nch) load(p);

    for (int i = 0; i < nch; i++) {
        const int bu = i % STAGES;
        const uint32_t ph = (uint32_t)((i / STAGES) & 1);
        mbar_wait(sbase + (uint32_t)bu * 16, ph);   // data of chunk i ready

        uint32_t base = sbase + MBAR_ZONE + (uint32_t)bu * BUFSZ;
        uint32_t aHp = base, aLp = base + TILE_A;
        uint32_t bHp = base + (SPLIT ? 2 * TILE_A : TILE_A);
        uint32_t bLp = base + 2 * TILE_A + TILE_B;

#pragma unroll
        for (int ks = 0; ks < 4; ks++) {
            const uint32_t kx = (uint32_t)(ks * 32);
            uint32_t Ahr[2][4], Alr[2][4], Bhr[NTB][2], Blr[NTB][2];
#pragma unroll
            for (int mt = 0; mt < 2; mt++) {
                ldsm4(Ahr[mt], aHp + (aoff0[mt] ^ kx));
                if (SPLIT) ldsm4(Alr[mt], aLp + (aoff0[mt] ^ kx));
            }
#pragma unroll
            for (int np = 0; np < NTB / 2; np++) {
                uint32_t q[4];
                ldsm4(q, bHp + (boff0[np] ^ kx));
                Bhr[np * 2][0] = q[0]; Bhr[np * 2][1] = q[1];
                Bhr[np * 2 + 1][0] = q[2]; Bhr[np * 2 + 1][1] = q[3];
                if (SPLIT) {
                    ldsm4(q, bLp + (boff0[np] ^ kx));
                    Blr[np * 2][0] = q[0]; Blr[np * 2][1] = q[1];
                    Blr[np * 2 + 1][0] = q[2]; Blr[np * 2 + 1][1] = q[3];
                }
            }
            if (ks == 3 && lane == 0)   // warp done reading buffer bu
                mbar_arrive(sbase + (uint32_t)bu * 16 + 8);

            if (SPLIT) {
#pragma unroll
                for (int mt = 0; mt < 2; mt++)
#pragma unroll
                    for (int nt = 0; nt < NTB; nt++)
                        mma_bf(acc[mt][nt], Ahr[mt], Bhr[nt]);
#pragma unroll
                for (int mt = 0; mt < 2; mt++)
#pragma unroll
                    for (int nt = 0; nt < NTB; nt++)
                        mma_bf(acc[mt][nt], Ahr[mt], Blr[nt]);
#pragma unroll
                for (int mt = 0; mt < 2; mt++)
#pragma unroll
                    for (int nt = 0; nt < NTB; nt++)
                        mma_bf(acc[mt][nt], Alr[mt], Bhr[nt]);
            } else {
#pragma unroll
                for (int mt = 0; mt < 2; mt++)
#pragma unroll
                    for (int nt = 0; nt < NTB; nt++)
                        mma_fp(acc[mt][nt], Ahr[mt], Bhr[nt]);
            }

            // producer: after first MMA bundle, stage chunk i + STAGES-1
            if (ks == 0) {
                int j = i + STAGES - 1;
                if (j < nch) {
                    int pj = j / STAGES;
                    if (pj > 0)   // wait for readers of this buffer's previous use
                        mbar_wait(sbase + (uint32_t)(j % STAGES) * 16 + 8,
                                  (uint32_t)((pj - 1) & 1));
                    load(j);
                }
            }
        }
    }
    __syncthreads();   // all warps done with tile buffers before stg reuse

    // ---- epilogue: stage through smem for coalesced writes (128 x LDC f32) --
    float* stg = (float*)(sgen + MBAR_ZONE);
#pragma unroll
    for (int mt = 0; mt < 2; mt++)
#pragma unroll
        for (int nt = 0; nt < NTB; nt++) {
            int r = wm + mt * 16 + (lane >> 2);
            int c = wn + nt * 8 + (lane & 3) * 2;
            stg[r * LDC + c]           = acc[mt][nt][0];
            stg[r * LDC + c + 1]       = acc[mt][nt][1];
            stg[(r + 8) * LDC + c]     = acc[mt][nt][2];
            stg[(r + 8) * LDC + c + 1] = acc[mt][nt][3];
        }
    __syncthreads();

    if (MODE == 0) {
        const float sc = g.scale[0];
        for (int e = tid; e < 128 * 64; e += NTHREADS) {
            int m = e >> 6, n = e & 63;
            size_t o = ((size_t)b * T_ + m0 + m) * E_ + n0 + n;
            float v = (stg[m * LDC + n] + g.bias[n0 + n] + g.xres[o]) * sc;
            bf16 h = __float2bfloat16(v);
            g.outH[o] = h;
            g.outL[o] = __float2bfloat16(v - __bfloat162float(h));
        }
    } else if (MODE == 1) {
        for (int e = tid; e < 128 * 64; e += NTHREADS) {
            int m = e >> 6, n = e & 63;
            g.outF[((size_t)b * T_ + m0 + m) * S_ + n0 + n] = stg[m * LDC + n];
        }
    } else if (MODE == 2) {
        __half* oh = (__half*)g.outH;
        for (int e = tid; e < 128 * 128; e += NTHREADS) {
            int m = e >> 7, n = e & 127;
            size_t o = ((size_t)b * T_ + m0 + m) * E_ + n0 + n;
            oh[o] = __float2half(stg[m * LDC + n]);
        }
    } else {
        for (int e = tid; e < 128 * 128; e += NTHREADS) {
            int n = e >> 7, m = e & 127;   // m fastest -> coalesced transposed store
            size_t o = ((size_t)b * C_ + n0 + n) * T_ + m0 + m;
            g.outF[o] = stg[m * LDC + n] + g.bias[n0 + n] + g.conved[o];
        }
    }
}

// ---------------- aux kernels -----------------------------------------------
__global__ __launch_bounds__(256) void convert_split2(
    const float4* __restrict__ in0, bf16* __restrict__ oh0, bf16* __restrict__ ol0, size_t n0,
    const float4* __restrict__ in1, bf16* __restrict__ oh1, bf16* __restrict__ ol1, size_t n1)
{
    size_t i = (size_t)blockIdx.x * 256 + threadIdx.x;
    const float4* in; bf16 *oh, *ol;
    if (i < n0)           { in = in0; oh = oh0; ol = ol0; }
    else if (i < n0 + n1) { i -= n0; in = in1; oh = oh1; ol = ol1; }
    else return;
    float4 f = in[i];
    bf16 h0 = __float2bfloat16(f.x), h1 = __float2bfloat16(f.y);
    bf16 h2 = __float2bfloat16(f.z), h3 = __float2bfloat16(f.w);
    ((__nv_bfloat162*)oh)[2 * i]     = {h0, h1};
    ((__nv_bfloat162*)oh)[2 * i + 1] = {h2, h3};
    ((__nv_bfloat162*)ol)[2 * i] =
        {__float2bfloat16(f.x - __bfloat162float(h0)),
         __float2bfloat16(f.y - __bfloat162float(h1))};
    ((__nv_bfloat162*)ol)[2 * i + 1] =
        {__float2bfloat16(f.z - __bfloat162float(h2)),
         __float2bfloat16(f.w - __bfloat162float(h3))};
}

__global__ __launch_bounds__(256) void convert_half(const float4* __restrict__ in,
                                                    __half* __restrict__ oh, size_t n4) {
    size_t i = (size_t)blockIdx.x * 256 + threadIdx.x;
    if (i >= n4) return;
    float4 f = in[i];
    ((__half2*)oh)[2 * i]     = {__float2half(f.x), __float2half(f.y)};
    ((__half2*)oh)[2 * i + 1] = {__float2half(f.z), __float2half(f.w)};
}

// in: [B][R][C] fp32 -> out: [B][C][R] bf16 hi/lo
__global__ __launch_bounds__(256) void transpose_split(const float* __restrict__ in,
                                                       bf16* __restrict__ oh,
                                                       bf16* __restrict__ ol,
                                                       int R, int C) {
    __shared__ float tile[32][33];
    const int bz = blockIdx.z;
    const float* src = in + (size_t)bz * R * C;
    const size_t ob = (size_t)bz * R * C;
    const int c0 = blockIdx.x * 32, r0 = blockIdx.y * 32;
    const int tx = threadIdx.x & 31, ty = threadIdx.x >> 5;
#pragma unroll
    for (int i = 0; i < 4; i++)
        tile[ty + i * 8][tx] = src[(size_t)(r0 + ty + i * 8) * C + c0 + tx];
    __syncthreads();
#pragma unroll
    for (int i = 0; i < 4; i++) {
        float v = tile[tx][ty + i * 8];
        size_t o = ob + (size_t)(c0 + ty + i * 8) * R + r0 + tx;
        bf16 h = __float2bfloat16(v);
        oh[o] = h;
        ol[o] = __float2bfloat16(v - __bfloat162float(h));
    }
}

// in: [B][R][C] fp32 -> out: [B][C][R] fp16
__global__ __launch_bounds__(256) void transpose_half(const float* __restrict__ in,
                                                      __half* __restrict__ oh,
                                                      int R, int C) {
    __shared__ float tile[32][33];
    const int bz = blockIdx.z;
    const float* src = in + (size_t)bz * R * C;
    const size_t ob = (size_t)bz * R * C;
    const int c0 = blockIdx.x * 32, r0 = blockIdx.y * 32;
    const int tx = threadIdx.x & 31, ty = threadIdx.x >> 5;
#pragma unroll
    for (int i = 0; i < 4; i++)
        tile[ty + i * 8][tx] = src[(size_t)(r0 + ty + i * 8) * C + c0 + tx];
    __syncthreads();
#pragma unroll
    for (int i = 0; i < 4; i++) {
        float v = tile[tx][ty + i * 8];
        size_t o = ob + (size_t)(c0 + ty + i * 8) * R + r0 + tx;
        oh[o] = __float2half(v);
    }
}

__global__ __launch_bounds__(256) void softmax_split(float* __restrict__ att,
                                                     __half* __restrict__ oh) {
    const size_t rb = (size_t)blockIdx.x * S_;
    float* p = att + rb;
    const int tid = threadIdx.x;
    __shared__ float red[8];

    float v[8];
    float mx = -1e30f;
#pragma unroll
    for (int i = 0; i < 8; i++) { v[i] = p[tid + i * 256]; mx = fmaxf(mx, v[i]); }
#pragma unroll
    for (int o = 16; o; o >>= 1) mx = fmaxf(mx, __shfl_xor_sync(0xffffffffu, mx, o));
    if ((tid & 31) == 0) red[tid >> 5] = mx;
    __syncthreads();
    float bm = red[0];
#pragma unroll
    for (int wi = 1; wi < 8; wi++) bm = fmaxf(bm, red[wi]);
    __syncthreads();

    float sum = 0.f;
#pragma unroll
    for (int i = 0; i < 8; i++) { v[i] = __expf(v[i] - bm); sum += v[i]; }
#pragma unroll
    for (int o = 16; o; o >>= 1) sum += __shfl_xor_sync(0xffffffffu, sum, o);
    if ((tid & 31) == 0) red[tid >> 5] = sum;
    __syncthreads();
    float bs = 0.f;
#pragma unroll
    for (int wi = 0; wi < 8; wi++) bs += red[wi];
    const float inv = 1.f / bs;
#pragma unroll
    for (int i = 0; i < 8; i++) {
        float pv = v[i] * inv;
        size_t o = rb + tid + i * 256;
        att[o] = pv;
        oh[o] = __float2half(pv);
    }
}

// ---------------- host -------------------------------------------------------
extern "C" void kernel_launch(void* const* d_in, const int* in_sizes, int n_in,
                              void* d_out, int out_size) {
    (void)in_sizes; (void)n_in; (void)out_size;
    const float* conved   = (const float*)d_in[0];
    const float* enc_conv = (const float*)d_in[1];
    const float* enc_comb = (const float*)d_in[2];
    const float* x        = (const float*)d_in[3];
    const float* scale    = (const float*)d_in[4];
    const float* W_h2e    = (const float*)d_in[5];
    const float* b_h2e    = (const float*)d_in[6];
    const float* W_e2h    = (const float*)d_in[7];
    const float* b_e2h    = (const float*)d_in[8];

    float* attn = (float*)d_out;
    float* out2 = (float*)d_out + (size_t)B_ * T_ * S_;

    bf16 *convT_h, *convT_l, *wh2e_h, *wh2e_l, *encK_h, *encK_l, *comb_h, *comb_l;
    __half *attn_h, *encVT_h, *attd_h, *we2h_h;
    cudaGetSymbolAddress((void**)&convT_h, g_convT_h);
    cudaGetSymbolAddress((void**)&convT_l, g_convT_l);
    cudaGetSymbolAddress((void**)&wh2e_h,  g_wh2e_h);
    cudaGetSymbolAddress((void**)&wh2e_l,  g_wh2e_l);
    cudaGetSymbolAddress((void**)&encK_h,  g_encK_h);
    cudaGetSymbolAddress((void**)&encK_l,  g_encK_l);
    cudaGetSymbolAddress((void**)&comb_h,  g_comb_h);
    cudaGetSymbolAddress((void**)&comb_l,  g_comb_l);
    cudaGetSymbolAddress((void**)&attn_h,  g_attn_h);
    cudaGetSymbolAddress((void**)&encVT_h, g_encVT_h);
    cudaGetSymbolAddress((void**)&attd_h,  g_attd_h);
    cudaGetSymbolAddress((void**)&we2h_h,  g_we2h_h);

    cudaFuncSetAttribute(mma_gemm<1,0>, cudaFuncAttributeMaxDynamicSharedMemorySize, SMEM_GEMM);
    cudaFuncSetAttribute(mma_gemm<1,1>, cudaFuncAttributeMaxDynamicSharedMemorySize, SMEM_GEMM);
    cudaFuncSetAttribute(mma_gemm<0,2>, cudaFuncAttributeMaxDynamicSharedMemorySize, SMEM_GEMM);
    cudaFuncSetAttribute(mma_gemm<0,3>, cudaFuncAttributeMaxDynamicSharedMemorySize, SMEM_GEMM);

    // --- preprocessing needed before G1/G2 ---
    transpose_split<<<dim3(T_/32, C_/32, B_), 256>>>(conved, convT_h, convT_l, C_, T_);
    {
        size_t n4w = (size_t)E_ * C_ / 4;
        size_t n4e = (size_t)B_ * S_ * E_ / 4;
        convert_split2<<<(unsigned)((n4w + n4e + 255) / 256), 256>>>(
            (const float4*)W_h2e, wh2e_h, wh2e_l, n4w,
            (const float4*)enc_conv, encK_h, encK_l, n4e);
        convert_half<<<(unsigned)((n4w + 255) / 256), 256>>>(
            (const float4*)W_e2h, we2h_h, n4w);
    }

    GemmArgs a{};

    // Stage 1 (bf16 split): comb = (convT @ W_h2e^T + b + x) * scale
    a = GemmArgs{convT_h, convT_l, wh2e_h, wh2e_l,
                 (long)T_ * C_, 0L, C_, C_, C_ / 64,
                 nullptr, comb_h, comb_l, b_h2e, x, scale, nullptr};
    mma_gemm<1,0><<<dim3(T_/128, E_/64, B_), NTHREADS, SMEM_GEMM>>>(a);

    // Stage 2 (bf16 split): energy = comb @ enc_conved^T -> fp32 in d_out
    a = GemmArgs{comb_h, comb_l, encK_h, encK_l,
                 (long)T_ * E_, (long)S_ * E_, E_, E_, E_ / 64,
                 attn, nullptr, nullptr, nullptr, nullptr, nullptr, nullptr};
    mma_gemm<1,1><<<dim3(T_/128, S_/64, B_), NTHREADS, SMEM_GEMM>>>(a);

    // Stage 3: softmax in place + fp16
    softmax_split<<<B_ * T_, 256>>>(attn, attn_h);

    // encVT transpose (fp16) only needed by stage 4
    transpose_half<<<dim3(E_/32, S_/32, B_), 256>>>(enc_comb, encVT_h, S_, E_);

    // Stage 4 (fp16 single): attended = attn @ enc_combined -> fp16
    a = GemmArgs{(const bf16*)attn_h, nullptr, (const bf16*)encVT_h, nullptr,
                 (long)T_ * S_, (long)E_ * S_, S_, S_, S_ / 64,
                 nullptr, (bf16*)attd_h, nullptr, nullptr, nullptr, nullptr, nullptr};
    mma_gemm<0,2><<<dim3(T_/128, E_/128, B_), NTHREADS, SMEM_GEMM>>>(a);

    // Stage 5 (fp16 single): out2[b,c,t] = attd @ W_e2h^T + b_e2h + conved
    a = GemmArgs{(const bf16*)attd_h, nullptr, (const bf16*)we2h_h, nullptr,
                 (long)T_ * E_, 0L, E_, E_, E_ / 64,
                 out2, nullptr, nullptr, b_e2h, nullptr, nullptr, conved};
    mma_gemm<0,3><<<dim3(T_/128, C_/128, B_), NTHREADS, SMEM_GEMM>>>(a);
}

// round 14
// speedup vs baseline: 1.1661x; 1.0031x over previous
#include <cuda_runtime.h>
#include <cuda_bf16.h>
#include <cuda_fp16.h>
#include <cstdint>

#define B_ 8
#define C_ 1024
#define T_ 2048
#define S_ 2048
#define E_ 1024

typedef __nv_bfloat16 bf16;

// ---------------- scratch (__device__ globals: allocation-free rule) -------
__device__ bf16 g_convT_h[(size_t)B_*T_*C_];
__device__ bf16 g_convT_l[(size_t)B_*T_*C_];
__device__ bf16 g_wh2e_h[(size_t)E_*C_];
__device__ bf16 g_wh2e_l[(size_t)E_*C_];
__device__ bf16 g_encK_h[(size_t)B_*S_*E_];
__device__ bf16 g_encK_l[(size_t)B_*S_*E_];
__device__ bf16 g_comb_h[(size_t)B_*T_*E_];
__device__ bf16 g_comb_l[(size_t)B_*T_*E_];
__device__ __half g_attn_h[(size_t)B_*T_*S_];   // fp16 single (V-path)
__device__ __half g_encVT_h[(size_t)B_*E_*S_];
__device__ __half g_attd_h[(size_t)B_*T_*E_];
__device__ __half g_we2h_h[(size_t)C_*E_];

// ---------------- helpers ----------------------------------------------------
__device__ __forceinline__ uint32_t smem_u32(const void* p) {
    uint32_t a;
    asm("{ .reg .u64 t; cvta.to.shared.u64 t, %1; cvt.u32.u64 %0, t; }"
        : "=r"(a) : "l"(p));
    return a;
}
__device__ __forceinline__ void cp16(uint32_t dst, const void* src) {
    asm volatile("cp.async.cg.shared.global [%0], [%1], 16;"
                 :: "r"(dst), "l"(src) : "memory");
}
__device__ __forceinline__ void mbar_init(uint32_t a, uint32_t cnt) {
    asm volatile("mbarrier.init.shared.b64 [%0], %1;" :: "r"(a), "r"(cnt) : "memory");
}
__device__ __forceinline__ void mbar_arrive(uint32_t a) {
    asm volatile("mbarrier.arrive.shared::cta.b64 _, [%0];" :: "r"(a) : "memory");
}
__device__ __forceinline__ void cpasync_arrive(uint32_t a) {
    asm volatile("cp.async.mbarrier.arrive.noinc.shared::cta.b64 [%0];"
                 :: "r"(a) : "memory");
}
__device__ __forceinline__ void mbar_wait(uint32_t a, uint32_t parity) {
    uint32_t done;
    do {
        asm volatile("{\n\t.reg .pred p;\n\t"
            "mbarrier.try_wait.parity.acquire.cta.shared::cta.b64 p, [%1], %2, 0x989680;\n\t"
            "selp.b32 %0, 1, 0, p;\n\t}"
            : "=r"(done) : "r"(a), "r"(parity) : "memory");
    } while (!done);
}
__device__ __forceinline__ void ldsm4(uint32_t* r, uint32_t a) {
    asm volatile("ldmatrix.sync.aligned.m8n8.x4.shared.b16 {%0,%1,%2,%3}, [%4];"
        : "=r"(r[0]), "=r"(r[1]), "=r"(r[2]), "=r"(r[3]) : "r"(a));
}
__device__ __forceinline__ void mma_bf(float* d, const uint32_t* a, const uint32_t* b) {
    asm volatile("mma.sync.aligned.m16n8k16.row.col.f32.bf16.bf16.f32 "
        "{%0,%1,%2,%3}, {%4,%5,%6,%7}, {%8,%9}, {%0,%1,%2,%3};"
        : "+f"(d[0]), "+f"(d[1]), "+f"(d[2]), "+f"(d[3])
        : "r"(a[0]), "r"(a[1]), "r"(a[2]), "r"(a[3]), "r"(b[0]), "r"(b[1]));
}
__device__ __forceinline__ void mma_fp(float* d, const uint32_t* a, const uint32_t* b) {
    asm volatile("mma.sync.aligned.m16n8k16.row.col.f32.f16.f16.f32 "
        "{%0,%1,%2,%3}, {%4,%5,%6,%7}, {%8,%9}, {%0,%1,%2,%3};"
        : "+f"(d[0]), "+f"(d[1]), "+f"(d[2]), "+f"(d[3])
        : "r"(a[0]), "r"(a[1]), "r"(a[2]), "r"(a[3]), "r"(b[0]), "r"(b[1]));
}

// SPLIT (bf16 3-term): CTA 128x64, 8 warps 4(m)x2(n), warp 32x32,
//                      K-chunk 32 (SW64, 64B rows), 4-stage pipe.
// SINGLE (fp16):       CTA 128x128, 8 warps 4(m)x2(n), warp 32x64,
//                      K-chunk 64 (SW128, 128B rows), 3-stage pipe.
// Both: 256 threads, 2 CTAs/SM.
#define NTHREADS 256
#define MBAR_ZONE 1024
#define SMEM_GEMM (1024 + MBAR_ZONE + 98304)

template <int ROWB>
__device__ __forceinline__ uint32_t swz(uint32_t bo) {
    return (ROWB == 128) ? (bo ^ ((bo >> 3) & 0x70))
                         : (bo ^ ((bo >> 3) & 0x30));
}

// async-load ROWS x (ROWB bytes) tile (k-contiguous source) into swizzled smem
template <int ROWS, int ROWB>
__device__ __forceinline__ void load_tile_async(const bf16* __restrict__ src,
                                                int row0, int ld, int k0,
                                                uint32_t sdst, int tid) {
    constexpr int SEGS = ROWB / 16;
#pragma unroll
    for (int r = 0; r < ROWS * SEGS / NTHREADS; r++) {
        int c = tid + r * NTHREADS;       // 16B chunks
        int row = c / SEGS, seg = c % SEGS;
        uint32_t bo = (uint32_t)(row * ROWB + seg * 16);
        cp16(sdst + swz<ROWB>(bo), src + (size_t)(row0 + row) * ld + k0 + seg * 8);
    }
}

// ---------------- GEMM args --------------------------------------------------
struct GemmArgs {
    const bf16 *Ah, *Al, *Bh, *Bl;   // 16-bit payload; type per SPLIT
    long sA, sB;
    int lda, ldb, nChunks;
    float* outF;
    bf16 *outH, *outL;
    const float *bias, *xres, *scale, *conved;
};

// MODE: 0 comb (bias+x,*scale -> bf16 hi/lo), 1 energy (fp32),
//       2 attd (fp16 single),  3 outproj (transposed +bias+residual fp32)
template <int SPLIT, int MODE>
__global__ __launch_bounds__(NTHREADS, 2) void mma_gemm(GemmArgs g) {
    extern __shared__ char sraw[];
    uint32_t sb0 = smem_u32(sraw);
    uint32_t sbase = (sb0 + 1023) & ~1023u;
    char* sgen = sraw + (sbase - sb0);

    constexpr int ROWB   = SPLIT ? 64 : 128;   // bytes per tile row
    constexpr int KCH    = SPLIT ? 32 : 64;    // K elems per chunk
    constexpr int KSC    = SPLIT ? 2 : 4;      // k16 steps per chunk
    constexpr int STAGES = SPLIT ? 4 : 3;
    constexpr int NTILE  = SPLIT ? 64 : 128;   // CTA n extent
    constexpr int NTB    = SPLIT ? 4 : 8;      // 8-col n-tiles per warp
    constexpr int LDC    = SPLIT ? 68 : 132;
    constexpr uint32_t TILE_A = 128u * ROWB;
    constexpr uint32_t TILE_B = (uint32_t)NTILE * ROWB;
    constexpr uint32_t BUFSZ = SPLIT ? (2 * TILE_A + 2 * TILE_B)   // 24KB
                                     : (TILE_A + TILE_B);          // 32KB

    const int tid = threadIdx.x;
    const int m0 = blockIdx.x * 128, n0 = blockIdx.y * NTILE, b = blockIdx.z;

    const bf16* Ah = g.Ah + (size_t)b * g.sA;
    const bf16* Al = SPLIT ? g.Al + (size_t)b * g.sA : nullptr;
    const bf16* Bh = g.Bh + (size_t)b * g.sB;
    const bf16* Bl = SPLIT ? g.Bl + (size_t)b * g.sB : nullptr;

    const int wid = tid >> 5, lane = tid & 31;
    const int wm = (wid & 3) * 32;                          // 4 m-warps
    const int wn = (wid >> 2) * (SPLIT ? 32 : 64);          // 2 n-warps

    // init pipeline mbarriers: full (cp.async-tracked, count=256),
    // empty (reader release, 1 arrive per warp -> count=8)
    if (tid == 0) {
#pragma unroll
        for (int s = 0; s < STAGES; s++) {
            mbar_init(sbase + s * 16,     NTHREADS);
            mbar_init(sbase + s * 16 + 8, 8);
        }
    }
    __syncthreads();

    float acc[2][NTB][4];
#pragma unroll
    for (int i = 0; i < 2; i++)
#pragma unroll
        for (int j = 0; j < NTB; j++)
#pragma unroll
            for (int k = 0; k < 4; k++) acc[i][j][k] = 0.f;

    // issue loads for chunk i + signal full[i%STAGES] on completion
    auto load = [&](int i) {
        int k0 = i * KCH;
        int bu = i % STAGES;
        uint32_t off = sbase + MBAR_ZONE + (uint32_t)bu * BUFSZ;
        if (SPLIT) {
            load_tile_async<128, ROWB>(Ah, m0, g.lda, k0, off,                        tid);
            load_tile_async<128, ROWB>(Al, m0, g.lda, k0, off + TILE_A,               tid);
            load_tile_async<64,  ROWB>(Bh, n0, g.ldb, k0, off + 2 * TILE_A,           tid);
            load_tile_async<64,  ROWB>(Bl, n0, g.ldb, k0, off + 2 * TILE_A + TILE_B,  tid);
        } else {
            load_tile_async<128, ROWB>(Ah, m0, g.lda, k0, off,          tid);
            load_tile_async<128, ROWB>(Bh, n0, g.ldb, k0, off + TILE_A, tid);
        }
        cpasync_arrive(sbase + (uint32_t)bu * 16);
    };

    // base swizzled offsets (ks=0); per-ks via XOR (ks*32) — the swizzle key
    // bits (7,8[,9]) are disjoint from bit 5, so XOR commutes with swizzle
    uint32_t aoff0[2], boff0[NTB / 2];
#pragma unroll
    for (int mt = 0; mt < 2; mt++)
        aoff0[mt] = swz<ROWB>((uint32_t)((wm + mt * 16 + (lane & 15)) * ROWB +
                                          (lane >> 4) * 16));
#pragma unroll
    for (int np = 0; np < NTB / 2; np++)
        boff0[np] = swz<ROWB>((uint32_t)((wn + np * 16 + (lane & 7) + (lane >> 4) * 8) * ROWB +
                                          ((lane >> 3) & 1) * 16));

    const int nch = g.nChunks;
#pragma unroll
    for (int p = 0; p < STAGES - 1; p++)
        if (p < nch) load(p);

    for (int i = 0; i < nch; i++) {
        const int bu = i % STAGES;
        const uint32_t ph = (uint32_t)((i / STAGES) & 1);
        mbar_wait(sbase + (uint32_t)bu * 16, ph);   // data of chunk i ready

        uint32_t base = sbase + MBAR_ZONE + (uint32_t)bu * BUFSZ;
        uint32_t aHp = base, aLp = base + TILE_A;
        uint32_t bHp = base + (SPLIT ? 2 * TILE_A : TILE_A);
        uint32_t bLp = base + 2 * TILE_A + TILE_B;

#pragma unroll
        for (int ks = 0; ks < KSC; ks++) {
            const uint32_t kx = (uint32_t)(ks * 32);
            uint32_t Ahr[2][4], Alr[2][4], Bhr[NTB][2], Blr[NTB][2];
#pragma unroll
            for (int mt = 0; mt < 2; mt++) {
                ldsm4(Ahr[mt], aHp + (aoff0[mt] ^ kx));
                if (SPLIT) ldsm4(Alr[mt], aLp + (aoff0[mt] ^ kx));
            }
#pragma unroll
            for (int np = 0; np < NTB / 2; np++) {
                uint32_t q[4];
                ldsm4(q, bHp + (boff0[np] ^ kx));
                Bhr[np * 2][0] = q[0]; Bhr[np * 2][1] = q[1];
                Bhr[np * 2 + 1][0] = q[2]; Bhr[np * 2 + 1][1] = q[3];
                if (SPLIT) {
                    ldsm4(q, bLp + (boff0[np] ^ kx));
                    Blr[np * 2][0] = q[0]; Blr[np * 2][1] = q[1];
                    Blr[np * 2 + 1][0] = q[2]; Blr[np * 2 + 1][1] = q[3];
                }
            }
            if (ks == KSC - 1 && lane == 0)   // warp done reading buffer bu
                mbar_arrive(sbase + (uint32_t)bu * 16 + 8);

            if (SPLIT) {
#pragma unroll
                for (int mt = 0; mt < 2; mt++)
#pragma unroll
                    for (int nt = 0; nt < NTB; nt++)
                        mma_bf(acc[mt][nt], Ahr[mt], Bhr[nt]);
#pragma unroll
                for (int mt = 0; mt < 2; mt++)
#pragma unroll
                    for (int nt = 0; nt < NTB; nt++)
                        mma_bf(acc[mt][nt], Ahr[mt], Blr[nt]);
#pragma unroll
                for (int mt = 0; mt < 2; mt++)
#pragma unroll
                    for (int nt = 0; nt < NTB; nt++)
                        mma_bf(acc[mt][nt], Alr[mt], Bhr[nt]);
            } else {
#pragma unroll
                for (int mt = 0; mt < 2; mt++)
#pragma unroll
                    for (int nt = 0; nt < NTB; nt++)
                        mma_fp(acc[mt][nt], Ahr[mt], Bhr[nt]);
            }

            // producer: after first MMA bundle, stage chunk i + STAGES-1
            if (ks == 0) {
                int j = i + STAGES - 1;
                if (j < nch) {
                    int pj = j / STAGES;
                    if (pj > 0)   // wait for readers of this buffer's previous use
                        mbar_wait(sbase + (uint32_t)(j % STAGES) * 16 + 8,
                                  (uint32_t)((pj - 1) & 1));
                    load(j);
                }
            }
        }
    }
    __syncthreads();   // all warps done with tile buffers before stg reuse

    // ---- epilogue: stage through smem for coalesced writes (128 x LDC f32) --
    float* stg = (float*)(sgen + MBAR_ZONE);
#pragma unroll
    for (int mt = 0; mt < 2; mt++)
#pragma unroll
        for (int nt = 0; nt < NTB; nt++) {
            int r = wm + mt * 16 + (lane >> 2);
            int c = wn + nt * 8 + (lane & 3) * 2;
            stg[r * LDC + c]           = acc[mt][nt][0];
            stg[r * LDC + c + 1]       = acc[mt][nt][1];
            stg[(r + 8) * LDC + c]     = acc[mt][nt][2];
            stg[(r + 8) * LDC + c + 1] = acc[mt][nt][3];
        }
    __syncthreads();

    if (MODE == 0) {
        const float sc = g.scale[0];
        for (int e = tid; e < 128 * 64; e += NTHREADS) {
            int m = e >> 6, n = e & 63;
            size_t o = ((size_t)b * T_ + m0 + m) * E_ + n0 + n;
            float v = (stg[m * LDC + n] + g.bias[n0 + n] + g.xres[o]) * sc;
            bf16 h = __float2bfloat16(v);
            g.outH[o] = h;
            g.outL[o] = __float2bfloat16(v - __bfloat162float(h));
        }
    } else if (MODE == 1) {
        for (int e = tid; e < 128 * 64; e += NTHREADS) {
            int m = e >> 6, n = e & 63;
            g.outF[((size_t)b * T_ + m0 + m) * S_ + n0 + n] = stg[m * LDC + n];
        }
    } else if (MODE == 2) {
        __half* oh = (__half*)g.outH;
        for (int e = tid; e < 128 * 128; e += NTHREADS) {
            int m = e >> 7, n = e & 127;
            size_t o = ((size_t)b * T_ + m0 + m) * E_ + n0 + n;
            oh[o] = __float2half(stg[m * LDC + n]);
        }
    } else {
        for (int e = tid; e < 128 * 128; e += NTHREADS) {
            int n = e >> 7, m = e & 127;   // m fastest -> coalesced transposed store
            size_t o = ((size_t)b * C_ + n0 + n) * T_ + m0 + m;
            g.outF[o] = stg[m * LDC + n] + g.bias[n0 + n] + g.conved[o];
        }
    }
}

// ---------------- aux kernels -----------------------------------------------
__global__ __launch_bounds__(256) void convert_split2(
    const float4* __restrict__ in0, bf16* __restrict__ oh0, bf16* __restrict__ ol0, size_t n0,
    const float4* __restrict__ in1, bf16* __restrict__ oh1, bf16* __restrict__ ol1, size_t n1)
{
    size_t i = (size_t)blockIdx.x * 256 + threadIdx.x;
    const float4* in; bf16 *oh, *ol;
    if (i < n0)           { in = in0; oh = oh0; ol = ol0; }
    else if (i < n0 + n1) { i -= n0; in = in1; oh = oh1; ol = ol1; }
    else return;
    float4 f = in[i];
    bf16 h0 = __float2bfloat16(f.x), h1 = __float2bfloat16(f.y);
    bf16 h2 = __float2bfloat16(f.z), h3 = __float2bfloat16(f.w);
    ((__nv_bfloat162*)oh)[2 * i]     = {h0, h1};
    ((__nv_bfloat162*)oh)[2 * i + 1] = {h2, h3};
    ((__nv_bfloat162*)ol)[2 * i] =
        {__float2bfloat16(f.x - __bfloat162float(h0)),
         __float2bfloat16(f.y - __bfloat162float(h1))};
    ((__nv_bfloat162*)ol)[2 * i + 1] =
        {__float2bfloat16(f.z - __bfloat162float(h2)),
         __float2bfloat16(f.w - __bfloat162float(h3))};
}

__global__ __launch_bounds__(256) void convert_half(const float4* __restrict__ in,
                                                    __half* __restrict__ oh, size_t n4) {
    size_t i = (size_t)blockIdx.x * 256 + threadIdx.x;
    if (i >= n4) return;
    float4 f = in[i];
    ((__half2*)oh)[2 * i]     = {__float2half(f.x), __float2half(f.y)};
    ((__half2*)oh)[2 * i + 1] = {__float2half(f.z), __float2half(f.w)};
}

// in: [B][R][C] fp32 -> out: [B][C][R] bf16 hi/lo
__global__ __launch_bounds__(256) void transpose_split(const float* __restrict__ in,
                                                       bf16* __restrict__ oh,
                                                       bf16* __restrict__ ol,
                                                       int R, int C) {
    __shared__ float tile[32][33];
    const int bz = blockIdx.z;
    const float* src = in + (size_t)bz * R * C;
    const size_t ob = (size_t)bz * R * C;
    const int c0 = blockIdx.x * 32, r0 = blockIdx.y * 32;
    const int tx = threadIdx.x & 31, ty = threadIdx.x >> 5;
#pragma unroll
    for (int i = 0; i < 4; i++)
        tile[ty + i * 8][tx] = src[(size_t)(r0 + ty + i * 8) * C + c0 + tx];
    __syncthreads();
#pragma unroll
    for (int i = 0; i < 4; i++) {
        float v = tile[tx][ty + i * 8];
        size_t o = ob + (size_t)(c0 + ty + i * 8) * R + r0 + tx;
        bf16 h = __float2bfloat16(v);
        oh[o] = h;
        ol[o] = __float2bfloat16(v - __bfloat162float(h));
    }
}

// in: [B][R][C] fp32 -> out: [B][C][R] fp16
__global__ __launch_bounds__(256) void transpose_half(const float* __restrict__ in,
                                                      __half* __restrict__ oh,
                                                      int R, int C) {
    __shared__ float tile[32][33];
    const int bz = blockIdx.z;
    const float* src = in + (size_t)bz * R * C;
    const size_t ob = (size_t)bz * R * C;
    const int c0 = blockIdx.x * 32, r0 = blockIdx.y * 32;
    const int tx = threadIdx.x & 31, ty = threadIdx.x >> 5;
#pragma unroll
    for (int i = 0; i < 4; i++)
        tile[ty + i * 8][tx] = src[(size_t)(r0 + ty + i * 8) * C + c0 + tx];
    __syncthreads();
#pragma unroll
    for (int i = 0; i < 4; i++) {
        float v = tile[tx][ty + i * 8];
        size_t o = ob + (size_t)(c0 + ty + i * 8) * R + r0 + tx;
        oh[o] = __float2half(v);
    }
}

__global__ __launch_bounds__(256) void softmax_split(float* __restrict__ att,
                                                     __half* __restrict__ oh) {
    const size_t rb = (size_t)blockIdx.x * S_;
    float* p = att + rb;
    const int tid = threadIdx.x;
    __shared__ float red[8];

    float v[8];
    float mx = -1e30f;
#pragma unroll
    for (int i = 0; i < 8; i++) { v[i] = p[tid + i * 256]; mx = fmaxf(mx, v[i]); }
#pragma unroll
    for (int o = 16; o; o >>= 1) mx = fmaxf(mx, __shfl_xor_sync(0xffffffffu, mx, o));
    if ((tid & 31) == 0) red[tid >> 5] = mx;
    __syncthreads();
    float bm = red[0];
#pragma unroll
    for (int wi = 1; wi < 8; wi++) bm = fmaxf(bm, red[wi]);
    __syncthreads();

    float sum = 0.f;
#pragma unroll
    for (int i = 0; i < 8; i++) { v[i] = __expf(v[i] - bm); sum += v[i]; }
#pragma unroll
    for (int o = 16; o; o >>= 1) sum += __shfl_xor_sync(0xffffffffu, sum, o);
    if ((tid & 31) == 0) red[tid >> 5] = sum;
    __syncthreads();
    float bs = 0.f;
#pragma unroll
    for (int wi = 0; wi < 8; wi++) bs += red[wi];
    const float inv = 1.f / bs;
#pragma unroll
    for (int i = 0; i < 8; i++) {
        float pv = v[i] * inv;
        size_t o = rb + tid + i * 256;
        att[o] = pv;
        oh[o] = __float2half(pv);
    }
}

// ---------------- host -------------------------------------------------------
extern "C" void kernel_launch(void* const* d_in, const int* in_sizes, int n_in,
                              void* d_out, int out_size) {
    (void)in_sizes; (void)n_in; (void)out_size;
    const float* conved   = (const float*)d_in[0];
    const float* enc_conv = (const float*)d_in[1];
    const float* enc_comb = (const float*)d_in[2];
    const float* x        = (const float*)d_in[3];
    const float* scale    = (const float*)d_in[4];
    const float* W_h2e    = (const float*)d_in[5];
    const float* b_h2e    = (const float*)d_in[6];
    const float* W_e2h    = (const float*)d_in[7];
    const float* b_e2h    = (const float*)d_in[8];

    float* attn = (float*)d_out;
    float* out2 = (float*)d_out + (size_t)B_ * T_ * S_;

    bf16 *convT_h, *convT_l, *wh2e_h, *wh2e_l, *encK_h, *encK_l, *comb_h, *comb_l;
    __half *attn_h, *encVT_h, *attd_h, *we2h_h;
    cudaGetSymbolAddress((void**)&convT_h, g_convT_h);
    cudaGetSymbolAddress((void**)&convT_l, g_convT_l);
    cudaGetSymbolAddress((void**)&wh2e_h,  g_wh2e_h);
    cudaGetSymbolAddress((void**)&wh2e_l,  g_wh2e_l);
    cudaGetSymbolAddress((void**)&encK_h,  g_encK_h);
    cudaGetSymbolAddress((void**)&encK_l,  g_encK_l);
    cudaGetSymbolAddress((void**)&comb_h,  g_comb_h);
    cudaGetSymbolAddress((void**)&comb_l,  g_comb_l);
    cudaGetSymbolAddress((void**)&attn_h,  g_attn_h);
    cudaGetSymbolAddress((void**)&encVT_h, g_encVT_h);
    cudaGetSymbolAddress((void**)&attd_h,  g_attd_h);
    cudaGetSymbolAddress((void**)&we2h_h,  g_we2h_h);

    cudaFuncSetAttribute(mma_gemm<1,0>, cudaFuncAttributeMaxDynamicSharedMemorySize, SMEM_GEMM);
    cudaFuncSetAttribute(mma_gemm<1,1>, cudaFuncAttributeMaxDynamicSharedMemorySize, SMEM_GEMM);
    cudaFuncSetAttribute(mma_gemm<0,2>, cudaFuncAttributeMaxDynamicSharedMemorySize, SMEM_GEMM);
    cudaFuncSetAttribute(mma_gemm<0,3>, cudaFuncAttributeMaxDynamicSharedMemorySize, SMEM_GEMM);

    // --- preprocessing needed before G1/G2 ---
    transpose_split<<<dim3(T_/32, C_/32, B_), 256>>>(conved, convT_h, convT_l, C_, T_);
    {
        size_t n4w = (size_t)E_ * C_ / 4;
        size_t n4e = (size_t)B_ * S_ * E_ / 4;
        convert_split2<<<(unsigned)((n4w + n4e + 255) / 256), 256>>>(
            (const float4*)W_h2e, wh2e_h, wh2e_l, n4w,
            (const float4*)enc_conv, encK_h, encK_l, n4e);
        convert_half<<<(unsigned)((n4w + 255) / 256), 256>>>(
            (const float4*)W_e2h, we2h_h, n4w);
    }

    GemmArgs a{};

    // Stage 1 (bf16 split, K-chunk 32): comb = (convT @ W_h2e^T + b + x) * scale
    a = GemmArgs{convT_h, convT_l, wh2e_h, wh2e_l,
                 (long)T_ * C_, 0L, C_, C_, C_ / 32,
                 nullptr, comb_h, comb_l, b_h2e, x, scale, nullptr};
    mma_gemm<1,0><<<dim3(T_/128, E_/64, B_), NTHREADS, SMEM_GEMM>>>(a);

    // Stage 2 (bf16 split, K-chunk 32): energy = comb @ enc_conved^T -> fp32
    a = GemmArgs{comb_h, comb_l, encK_h, encK_l,
                 (long)T_ * E_, (long)S_ * E_, E_, E_, E_ / 32,
                 attn, nullptr, nullptr, nullptr, nullptr, nullptr, nullptr};
    mma_gemm<1,1><<<dim3(T_/128, S_/64, B_), NTHREADS, SMEM_GEMM>>>(a);

    // Stage 3: softmax in place + fp16
    softmax_split<<<B_ * T_, 256>>>(attn, attn_h);

    // encVT transpose (fp16) only needed by stage 4
    transpose_half<<<dim3(E_/32, S_/32, B_), 256>>>(enc_comb, encVT_h, S_, E_);

    // Stage 4 (fp16 single, K-chunk 64): attended = attn @ enc_combined -> fp16
    a = GemmArgs{(const bf16*)attn_h, nullptr, (const bf16*)encVT_h, nullptr,
                 (long)T_ * S_, (long)E_ * S_, S_, S_, S_ / 64,
                 nullptr, (bf16*)attd_h, nullptr, nullptr, nullptr, nullptr, nullptr};
    mma_gemm<0,2><<<dim3(T_/128, E_/128, B_), NTHREADS, SMEM_GEMM>>>(a);

    // Stage 5 (fp16 single, K-chunk 64): out2[b,c,t] = attd @ W_e2h^T + b + conved
    a = GemmArgs{(const bf16*)attd_h, nullptr, (const bf16*)we2h_h, nullptr,
                 (long)T_ * E_, 0L, E_, E_, E_ / 64,
                 out2, nullptr, nullptr, b_e2h, nullptr, nullptr, conved};
    mma_gemm<0,3><<<dim3(T_/128, C_/128, B_), NTHREADS, SMEM_GEMM>>>(a);
}